// round 5
// baseline (speedup 1.0000x reference)
#include <cuda_runtime.h>
#include <cuda_bf16.h>

// out[(half*128 + 2f), i]   = sin(coord[half][i] * inv_freq[f])
// out[(half*128 + 2f+1), i] = cos(coord[half][i] * inv_freq[f])
// half = 0 -> Y rows (0..127), half = 1 -> X rows (128..255).
//
// R5: R4 + __launch_bounds__(256, 8) to cap regs at 32 -> 8 CTAs/SM,
//     100% theoretical occupancy, more store MLP resident per SM.

#define FPG 8   // freqs per CTA group

__global__ __launch_bounds__(256, 8)
void pe_offgrid_kernel(const float* __restrict__ YX,
                       const float* __restrict__ inv_freq,
                       float* __restrict__ out,
                       int num) {
    int g = blockIdx.y;                 // 0..(2*64/FPG - 1)
    int half = g >= (64 / FPG);         // 0 or 1
    int fbase = (g - half * (64 / FPG)) * FPG;

    int i0 = (blockIdx.x * blockDim.x + threadIdx.x) << 2;  // 4 elems/thread

    const float4 c4 = *reinterpret_cast<const float4*>(YX + (size_t)half * num + i0);

    float* hbase = out + (size_t)(half * 128 + 2 * fbase) * (size_t)num + i0;

    #pragma unroll
    for (int k = 0; k < FPG; k++) {
        float freq = __ldg(inv_freq + fbase + k);
        float4 s, c;
        __sincosf(c4.x * freq, &s.x, &c.x);
        __sincosf(c4.y * freq, &s.y, &c.y);
        __sincosf(c4.z * freq, &s.z, &c.z);
        __sincosf(c4.w * freq, &s.w, &c.w);
        float* row = hbase + (size_t)(2 * k) * (size_t)num;
        __stcs(reinterpret_cast<float4*>(row), s);        // sin row (streaming)
        __stcs(reinterpret_cast<float4*>(row + num), c);  // cos row (streaming)
    }
}

extern "C" void kernel_launch(void* const* d_in, const int* in_sizes, int n_in,
                              void* d_out, int out_size) {
    const float* YX       = (const float*)d_in[0];   // (2, num) fp32
    const float* inv_freq = (const float*)d_in[1];   // (64,)   fp32
    float* out            = (float*)d_out;           // (256, num) fp32

    int num = in_sizes[0] / 2;                       // 262144

    const int TPB = 256;
    int i_blocks = num / (TPB * 4);                  // 256
    dim3 grid(i_blocks, 2 * 64 / FPG);               // 256 x 16 = 4096 CTAs
    pe_offgrid_kernel<<<grid, TPB>>>(YX, inv_freq, out, num);
}